// round 1
// baseline (speedup 1.0000x reference)
#include <cuda_runtime.h>
#include <cuda_bf16.h>

#define TOKENS  256
#define NOUT    4096
#define NIN     4096
#define NSPARSE 8388608

// Dense reconstructed weight matrix, 64 MB scratch (allocation-free rule:
// __device__ global, not cudaMalloc).
__device__ float d_W[(size_t)NOUT * NIN];

// ---------------------------------------------------------------------------
// Stage 1: zero W. 16,777,216 floats = 4,194,304 float4 = 16384 blocks x 256.
// ---------------------------------------------------------------------------
__global__ void zero_w_kernel() {
    size_t i = (size_t)blockIdx.x * blockDim.x + threadIdx.x;
    reinterpret_cast<float4*>(d_W)[i] = make_float4(0.f, 0.f, 0.f, 0.f);
}

// ---------------------------------------------------------------------------
// Stage 2: scatter sparse values. flat_idx is sorted ascending, so writes from
// consecutive threads land on adjacent cache lines (50% density) — near-coalesced.
// NSPARSE = 32768 * 256 exactly.
// ---------------------------------------------------------------------------
__global__ void scatter_kernel(const float* __restrict__ vals,
                               const int*   __restrict__ idx) {
    int i = blockIdx.x * blockDim.x + threadIdx.x;
    d_W[(size_t)(unsigned)idx[i]] = vals[i];
}

// ---------------------------------------------------------------------------
// Stage 3: out[m,n] = sum_k x[m,k] * W[n,k]   (NT GEMM, both operands K-major)
// 64x64 tile, BK=16, 256 threads, 4x4 micro-tile per thread.
// ---------------------------------------------------------------------------
constexpr int BM = 64;
constexpr int BN = 64;
constexpr int BK = 16;

__global__ __launch_bounds__(256, 2)
void gemm_nt_kernel(const float* __restrict__ x, float* __restrict__ out) {
    // +4 pad keeps rows 16B-aligned (68*4 = 272 = 17*16) and reduces STS conflicts.
    __shared__ float As[BK][BM + 4];
    __shared__ float Bs[BK][BN + 4];

    const int tid = threadIdx.x;
    const int bm  = blockIdx.y * BM;   // token-tile base
    const int bn  = blockIdx.x * BN;   // output-row tile base
    const int ty  = tid >> 4;          // 0..15  (M direction)
    const int tx  = tid & 15;          // 0..15  (N direction)

    // Global-load assignment: each thread fetches one float4 (4 consecutive K)
    // of one row for each of A and B per K-tile.
    const int lrow = tid >> 2;         // 0..63
    const int lk   = (tid & 3) << 2;   // 0,4,8,12

    const float* xg = x   + (size_t)(bm + lrow) * NIN + lk;
    const float* wg = d_W + (size_t)(bn + lrow) * NIN + lk;

    float acc[4][4] = {};

    for (int k0 = 0; k0 < NIN; k0 += BK) {
        const float4 av = *reinterpret_cast<const float4*>(xg + k0);
        const float4 bv = *reinterpret_cast<const float4*>(wg + k0);

        __syncthreads();   // protect previous iteration's smem reads
        As[lk + 0][lrow] = av.x;
        As[lk + 1][lrow] = av.y;
        As[lk + 2][lrow] = av.z;
        As[lk + 3][lrow] = av.w;
        Bs[lk + 0][lrow] = bv.x;
        Bs[lk + 1][lrow] = bv.y;
        Bs[lk + 2][lrow] = bv.z;
        Bs[lk + 3][lrow] = bv.w;
        __syncthreads();

#pragma unroll
        for (int k = 0; k < BK; ++k) {
            const float4 a4 = *reinterpret_cast<const float4*>(&As[k][ty * 4]);
            const float4 b4 = *reinterpret_cast<const float4*>(&Bs[k][tx * 4]);
            const float a[4] = {a4.x, a4.y, a4.z, a4.w};
            const float b[4] = {b4.x, b4.y, b4.z, b4.w};
#pragma unroll
            for (int i = 0; i < 4; ++i)
#pragma unroll
                for (int j = 0; j < 4; ++j)
                    acc[i][j] += a[i] * b[j];
        }
    }

#pragma unroll
    for (int i = 0; i < 4; ++i) {
        const int row = bm + ty * 4 + i;
        const float4 o = make_float4(acc[i][0], acc[i][1], acc[i][2], acc[i][3]);
        *reinterpret_cast<float4*>(&out[(size_t)row * NOUT + bn + tx * 4]) = o;
    }
}

// ---------------------------------------------------------------------------
// Launch: zero -> scatter -> gemm, all on the default stream (ordered),
// graph-capturable (kernel launches only, no sync, no alloc).
// ---------------------------------------------------------------------------
extern "C" void kernel_launch(void* const* d_in, const int* in_sizes, int n_in,
                              void* d_out, int out_size) {
    const float* x    = (const float*)d_in[0];
    const float* vals = (const float*)d_in[1];
    const int*   idx  = (const int*)d_in[2];
    float*       out  = (float*)d_out;

    zero_w_kernel<<<(NOUT * (size_t)NIN / 4) / 256, 256>>>();
    scatter_kernel<<<NSPARSE / 256, 256>>>(vals, idx);

    dim3 grid(NOUT / BN, TOKENS / BM);
    gemm_nt_kernel<<<grid, 256>>>(x, out);
}

// round 3
// speedup vs baseline: 1.7941x; 1.7941x over previous
#include <cuda_runtime.h>
#include <cuda_bf16.h>
#include <cstdint>

#define TOKENS  256
#define NOUT    4096
#define NIN     4096
#define NSPARSE 8388608

// ---------------------------------------------------------------------------
// Scratch (allocation-free rule: __device__ globals)
// ---------------------------------------------------------------------------
__device__ __nv_bfloat16 d_Whi[(size_t)NOUT * NIN];   // 32 MB
__device__ __nv_bfloat16 d_Wlo[(size_t)NOUT * NIN];   // 32 MB
__device__ __nv_bfloat16 d_xhi[TOKENS * NIN];
__device__ __nv_bfloat16 d_xlo[TOKENS * NIN];

// ---------------------------------------------------------------------------
// Stage 1: fused scatter + gap zero-fill. flat_idx sorted unique ascending:
// thread i owns [idx[i], idx[i+1]) — value at idx[i], zeros after. Thread 0
// also zeros [0, idx[0]). No separate 64MB zeroing pass.
// ---------------------------------------------------------------------------
__global__ void scatter_fill_kernel(const float* __restrict__ vals,
                                    const int*   __restrict__ idx) {
    int i = blockIdx.x * blockDim.x + threadIdx.x;
    int cur = idx[i];
    int nxt = (i + 1 < NSPARSE) ? idx[i + 1] : (NOUT * NIN);
    float v = vals[i];
    __nv_bfloat16 hi = __float2bfloat16(v);
    __nv_bfloat16 lo = __float2bfloat16(v - __bfloat162float(hi));
    d_Whi[cur] = hi;
    d_Wlo[cur] = lo;
    const __nv_bfloat16 z = __float2bfloat16(0.0f);
    for (int p = cur + 1; p < nxt; ++p) { d_Whi[p] = z; d_Wlo[p] = z; }
    if (i == 0) {
        for (int p = 0; p < cur; ++p) { d_Whi[p] = z; d_Wlo[p] = z; }
    }
}

// ---------------------------------------------------------------------------
// Stage 2: split x into bf16 hi/lo.
// ---------------------------------------------------------------------------
__global__ void xsplit_kernel(const float* __restrict__ x) {
    int i = blockIdx.x * blockDim.x + threadIdx.x;
    float v = x[i];
    __nv_bfloat16 hi = __float2bfloat16(v);
    d_xhi[i] = hi;
    d_xlo[i] = __float2bfloat16(v - __bfloat162float(hi));
}

// ---------------------------------------------------------------------------
// Stage 3: HMMA (mma.sync m16n8k16 bf16) NT GEMM, out = x @ W^T.
// CTA 128x64, BK=32, 256 threads (8 warps, 4x2), 4-stage cp.async pipeline.
// 3 products per K-slice: hi*hi + hi*lo + lo*hi (fp32 accum).
// ---------------------------------------------------------------------------
constexpr int BM = 128;
constexpr int BN = 64;
constexpr int BK = 32;
constexpr int STAGES  = 4;
constexpr int NKT     = NIN / BK;        // 128 k-tiles
constexpr int LDH     = BK + 8;          // 40 halves/row (80B) -> conflict-free ldmatrix
constexpr int A_H     = BM * LDH;        // 5120 halves per A tile
constexpr int B_H     = BN * LDH;        // 2560 halves per B tile
constexpr int STG_H   = 2 * A_H + 2 * B_H;   // Ahi,Alo,Bhi,Blo = 15360 halves
constexpr int OFF_AHI = 0;
constexpr int OFF_ALO = A_H;
constexpr int OFF_BHI = 2 * A_H;
constexpr int OFF_BLO = 2 * A_H + B_H;
constexpr int SMEM_BYTES = STAGES * STG_H * 2;   // 122880

__device__ __forceinline__ uint32_t smem_u32(const void* p) {
    uint32_t a;
    asm("{ .reg .u64 t; cvta.to.shared.u64 t, %1; cvt.u32.u64 %0, t; }" : "=r"(a) : "l"(p));
    return a;
}
__device__ __forceinline__ void cp16(uint32_t dst, const void* src) {
    asm volatile("cp.async.cg.shared.global [%0], [%1], 16;" :: "r"(dst), "l"(src));
}
__device__ __forceinline__ void ldsm4(uint32_t r[4], uint32_t addr) {
    asm volatile("ldmatrix.sync.aligned.m8n8.x4.shared.b16 {%0,%1,%2,%3},[%4];"
                 : "=r"(r[0]), "=r"(r[1]), "=r"(r[2]), "=r"(r[3]) : "r"(addr));
}
__device__ __forceinline__ void mma_bf16(float c[4], const uint32_t a[4],
                                         uint32_t b0, uint32_t b1) {
    asm volatile(
        "mma.sync.aligned.m16n8k16.row.col.f32.bf16.bf16.f32 "
        "{%0,%1,%2,%3},{%4,%5,%6,%7},{%8,%9},{%0,%1,%2,%3};"
        : "+f"(c[0]), "+f"(c[1]), "+f"(c[2]), "+f"(c[3])
        : "r"(a[0]), "r"(a[1]), "r"(a[2]), "r"(a[3]), "r"(b0), "r"(b1));
}

__global__ void __launch_bounds__(256, 1)
gemm_hmma_kernel(float* __restrict__ out) {
    extern __shared__ __nv_bfloat16 sh[];
    const uint32_t sbase = smem_u32(sh);

    const int tid  = threadIdx.x;
    const int lane = tid & 31;
    const int wid  = tid >> 5;
    const int mw   = wid >> 1;           // 0..3  (M warp)
    const int nw   = wid & 1;            // 0..1  (N warp)
    const int bm   = blockIdx.y * BM;
    const int bn   = blockIdx.x * BN;

    // --- cp.async source/dest assignment -----------------------------------
    // A tile: 512 16B-chunks (c: row=c>>2, kblk=(c&3)*8). Thread t: c=t, t+256.
    // B tile: 256 chunks, thread t: c=t.
    const int ar0 = tid >> 2,          akb0 = (tid & 3) * 8;
    const int ar1 = (tid + 256) >> 2,  akb1 = akb0;        // same (t&3)
    const int br  = tid >> 2,          bkb  = (tid & 3) * 8;

    const __nv_bfloat16* gAhi0 = d_xhi + (size_t)(bm + ar0) * NIN + akb0;
    const __nv_bfloat16* gAlo0 = d_xlo + (size_t)(bm + ar0) * NIN + akb0;
    const __nv_bfloat16* gAhi1 = d_xhi + (size_t)(bm + ar1) * NIN + akb1;
    const __nv_bfloat16* gAlo1 = d_xlo + (size_t)(bm + ar1) * NIN + akb1;
    const __nv_bfloat16* gBhi  = d_Whi + (size_t)(bn + br) * NIN + bkb;
    const __nv_bfloat16* gBlo  = d_Wlo + (size_t)(bn + br) * NIN + bkb;

    const uint32_t dA0 = (uint32_t)(ar0 * LDH + akb0) * 2;
    const uint32_t dA1 = (uint32_t)(ar1 * LDH + akb1) * 2;
    const uint32_t dB  = (uint32_t)(br  * LDH + bkb)  * 2;

#define ISSUE(kk)                                                              \
    do {                                                                       \
        const uint32_t st_ = sbase + (uint32_t)((kk) & (STAGES - 1)) * (STG_H * 2); \
        const int kg_ = (kk) * BK;                                             \
        cp16(st_ + OFF_AHI * 2 + dA0, gAhi0 + kg_);                            \
        cp16(st_ + OFF_AHI * 2 + dA1, gAhi1 + kg_);                            \
        cp16(st_ + OFF_ALO * 2 + dA0, gAlo0 + kg_);                            \
        cp16(st_ + OFF_ALO * 2 + dA1, gAlo1 + kg_);                            \
        cp16(st_ + OFF_BHI * 2 + dB,  gBhi  + kg_);                            \
        cp16(st_ + OFF_BLO * 2 + dB,  gBlo  + kg_);                            \
        asm volatile("cp.async.commit_group;" ::: "memory");                   \
    } while (0)

    // --- ldmatrix per-lane byte offsets (within a tile region) -------------
    // A frag (f, kslice s): row = mw*32 + f*16 + (lane&15), koff8 = (lane>>4)*8
    // Tiles land as a0..a3 in mma order.
    uint32_t aoff[2][2];
#pragma unroll
    for (int f = 0; f < 2; ++f)
#pragma unroll
        for (int s = 0; s < 2; ++s)
            aoff[f][s] = (uint32_t)((mw * 32 + f * 16 + (lane & 15)) * LDH
                                    + s * 16 + (lane >> 4) * 8) * 2;
    // B pair (p covers n-frags 2p,2p+1): row n = nw*32 + p*16 + (lane&7) + ((lane&16)>>1)
    // koff8 = ((lane>>3)&1)*8  -> regs {f0.b0, f0.b1, f1.b0, f1.b1}
    uint32_t boff[2][2];
#pragma unroll
    for (int p = 0; p < 2; ++p)
#pragma unroll
        for (int s = 0; s < 2; ++s)
            boff[p][s] = (uint32_t)((nw * 32 + p * 16 + (lane & 7) + ((lane & 16) >> 1)) * LDH
                                    + s * 16 + (((lane >> 3) & 1) * 8)) * 2;

    float acc[2][4][4] = {};

    ISSUE(0); ISSUE(1); ISSUE(2);

    for (int k = 0; k < NKT; ++k) {
        asm volatile("cp.async.wait_group 2;" ::: "memory");
        __syncthreads();

        if (k + 3 < NKT) ISSUE(k + 3);
        else asm volatile("cp.async.commit_group;" ::: "memory");  // keep group count exact

        const uint32_t st = sbase + (uint32_t)(k & (STAGES - 1)) * (STG_H * 2);
        const uint32_t ahi_b = st + OFF_AHI * 2, alo_b = st + OFF_ALO * 2;
        const uint32_t bhi_b = st + OFF_BHI * 2, blo_b = st + OFF_BLO * 2;

#pragma unroll
        for (int s = 0; s < 2; ++s) {            // two k16 slices per BK=32
            uint32_t a_hi[2][4], a_lo[2][4], b_hi[2][4], b_lo[2][4];
            ldsm4(a_hi[0], ahi_b + aoff[0][s]);
            ldsm4(a_hi[1], ahi_b + aoff[1][s]);
            ldsm4(a_lo[0], alo_b + aoff[0][s]);
            ldsm4(a_lo[1], alo_b + aoff[1][s]);
            ldsm4(b_hi[0], bhi_b + boff[0][s]);
            ldsm4(b_hi[1], bhi_b + boff[1][s]);
            ldsm4(b_lo[0], blo_b + boff[0][s]);
            ldsm4(b_lo[1], blo_b + boff[1][s]);
#pragma unroll
            for (int mf = 0; mf < 2; ++mf)
#pragma unroll
                for (int nf = 0; nf < 4; ++nf) {
                    const int p = nf >> 1, q = (nf & 1) * 2;
                    mma_bf16(acc[mf][nf], a_hi[mf], b_hi[p][q], b_hi[p][q + 1]);
                    mma_bf16(acc[mf][nf], a_hi[mf], b_lo[p][q], b_lo[p][q + 1]);
                    mma_bf16(acc[mf][nf], a_lo[mf], b_hi[p][q], b_hi[p][q + 1]);
                }
        }
        __syncthreads();   // all warps done with stage k before it is rewritten
    }
#undef ISSUE

    // --- epilogue: fragment -> gmem (float2 stores) -------------------------
#pragma unroll
    for (int mf = 0; mf < 2; ++mf) {
        const int row0 = bm + mw * 32 + mf * 16 + (lane >> 2);
#pragma unroll
        for (int nf = 0; nf < 4; ++nf) {
            const int col = bn + nw * 32 + nf * 8 + (lane & 3) * 2;
            *reinterpret_cast<float2*>(&out[(size_t)row0 * NOUT + col]) =
                make_float2(acc[mf][nf][0], acc[mf][nf][1]);
            *reinterpret_cast<float2*>(&out[(size_t)(row0 + 8) * NOUT + col]) =
                make_float2(acc[mf][nf][2], acc[mf][nf][3]);
        }
    }
}

// ---------------------------------------------------------------------------
// Launch: scatter+fill -> xsplit -> HMMA GEMM (default stream, capturable)
// ---------------------------------------------------------------------------
extern "C" void kernel_launch(void* const* d_in, const int* in_sizes, int n_in,
                              void* d_out, int out_size) {
    const float* x    = (const float*)d_in[0];
    const float* vals = (const float*)d_in[1];
    const int*   idx  = (const int*)d_in[2];
    float*       out  = (float*)d_out;

    scatter_fill_kernel<<<NSPARSE / 256, 256>>>(vals, idx);
    xsplit_kernel<<<(TOKENS * NIN) / 256, 256>>>(x);

    static bool configured = false;
    if (!configured) {
        cudaFuncSetAttribute(gemm_hmma_kernel,
                             cudaFuncAttributeMaxDynamicSharedMemorySize, SMEM_BYTES);
        configured = true;
    }
    dim3 grid(NOUT / BN, TOKENS / BM);   // 64 x 2 = 128 CTAs
    gemm_hmma_kernel<<<grid, 256, SMEM_BYTES>>>(out);
}

// round 4
// speedup vs baseline: 1.9687x; 1.0973x over previous
#include <cuda_runtime.h>
#include <cuda_bf16.h>
#include <cstdint>

#define TOKENS  256
#define NOUT    4096
#define NIN     4096
#define NSPARSE 8388608

// ---------------------------------------------------------------------------
// Scratch (allocation-free rule: __device__ globals)
// ---------------------------------------------------------------------------
__device__ __nv_bfloat16 d_Whi[(size_t)NOUT * NIN];   // 32 MB
__device__ __nv_bfloat16 d_Wlo[(size_t)NOUT * NIN];   // 32 MB
__device__ __nv_bfloat16 d_xhi[TOKENS * NIN];
__device__ __nv_bfloat16 d_xlo[TOKENS * NIN];

// ---------------------------------------------------------------------------
// Stage 0: zero both W arrays with 16B stores (DRAM-bound, ~12us).
// 64MB / 16B = 4,194,304 stores; grid 16384 x 256, 1 store/thread.
// ---------------------------------------------------------------------------
__global__ void zero_w_kernel() {
    const size_t i = (size_t)blockIdx.x * blockDim.x + threadIdx.x;
    const uint4 z = make_uint4(0u, 0u, 0u, 0u);
    const size_t half = (size_t)NOUT * NIN / 8;   // uint4 count per array
    if (i < half) reinterpret_cast<uint4*>(d_Whi)[i] = z;
    else          reinterpret_cast<uint4*>(d_Wlo)[i - half] = z;
}

// ---------------------------------------------------------------------------
// Stage 1: scatter sparse values (no gap fill — zero pass handles gaps).
// 4 elements per thread via int4/float4 loads; 2x 2B stores per element.
// Sorted idx at 50% density -> warp's stores land in ~2 sectors per array.
// ---------------------------------------------------------------------------
__global__ void scatter_kernel(const float* __restrict__ vals,
                               const int*   __restrict__ idx) {
    const int i = blockIdx.x * blockDim.x + threadIdx.x;   // < NSPARSE/4
    const int4   ix = reinterpret_cast<const int4*>(idx)[i];
    const float4 v  = reinterpret_cast<const float4*>(vals)[i];

    {
        __nv_bfloat16 hi = __float2bfloat16(v.x);
        d_Whi[(unsigned)ix.x] = hi;
        d_Wlo[(unsigned)ix.x] = __float2bfloat16(v.x - __bfloat162float(hi));
    }
    {
        __nv_bfloat16 hi = __float2bfloat16(v.y);
        d_Whi[(unsigned)ix.y] = hi;
        d_Wlo[(unsigned)ix.y] = __float2bfloat16(v.y - __bfloat162float(hi));
    }
    {
        __nv_bfloat16 hi = __float2bfloat16(v.z);
        d_Whi[(unsigned)ix.z] = hi;
        d_Wlo[(unsigned)ix.z] = __float2bfloat16(v.z - __bfloat162float(hi));
    }
    {
        __nv_bfloat16 hi = __float2bfloat16(v.w);
        d_Whi[(unsigned)ix.w] = hi;
        d_Wlo[(unsigned)ix.w] = __float2bfloat16(v.w - __bfloat162float(hi));
    }
}

// ---------------------------------------------------------------------------
// Stage 2: split x into bf16 hi/lo.
// ---------------------------------------------------------------------------
__global__ void xsplit_kernel(const float* __restrict__ x) {
    int i = blockIdx.x * blockDim.x + threadIdx.x;
    float v = x[i];
    __nv_bfloat16 hi = __float2bfloat16(v);
    d_xhi[i] = hi;
    d_xlo[i] = __float2bfloat16(v - __bfloat162float(hi));
}

// ---------------------------------------------------------------------------
// Stage 3: HMMA (mma.sync m16n8k16 bf16) NT GEMM, out = x @ W^T.
// CTA 128x64, BK=32, 256 threads (8 warps, 4x2), 4-stage cp.async pipeline.
// 3 products per K-slice: hi*hi + hi*lo + lo*hi (fp32 accum).  (unchanged)
// ---------------------------------------------------------------------------
constexpr int BM = 128;
constexpr int BN = 64;
constexpr int BK = 32;
constexpr int STAGES  = 4;
constexpr int NKT     = NIN / BK;        // 128 k-tiles
constexpr int LDH     = BK + 8;          // 40 halves/row (80B) -> conflict-free ldmatrix
constexpr int A_H     = BM * LDH;
constexpr int B_H     = BN * LDH;
constexpr int STG_H   = 2 * A_H + 2 * B_H;
constexpr int OFF_AHI = 0;
constexpr int OFF_ALO = A_H;
constexpr int OFF_BHI = 2 * A_H;
constexpr int OFF_BLO = 2 * A_H + B_H;
constexpr int SMEM_BYTES = STAGES * STG_H * 2;   // 122880

__device__ __forceinline__ uint32_t smem_u32(const void* p) {
    uint32_t a;
    asm("{ .reg .u64 t; cvta.to.shared.u64 t, %1; cvt.u32.u64 %0, t; }" : "=r"(a) : "l"(p));
    return a;
}
__device__ __forceinline__ void cp16(uint32_t dst, const void* src) {
    asm volatile("cp.async.cg.shared.global [%0], [%1], 16;" :: "r"(dst), "l"(src));
}
__device__ __forceinline__ void ldsm4(uint32_t r[4], uint32_t addr) {
    asm volatile("ldmatrix.sync.aligned.m8n8.x4.shared.b16 {%0,%1,%2,%3},[%4];"
                 : "=r"(r[0]), "=r"(r[1]), "=r"(r[2]), "=r"(r[3]) : "r"(addr));
}
__device__ __forceinline__ void mma_bf16(float c[4], const uint32_t a[4],
                                         uint32_t b0, uint32_t b1) {
    asm volatile(
        "mma.sync.aligned.m16n8k16.row.col.f32.bf16.bf16.f32 "
        "{%0,%1,%2,%3},{%4,%5,%6,%7},{%8,%9},{%0,%1,%2,%3};"
        : "+f"(c[0]), "+f"(c[1]), "+f"(c[2]), "+f"(c[3])
        : "r"(a[0]), "r"(a[1]), "r"(a[2]), "r"(a[3]), "r"(b0), "r"(b1));
}

__global__ void __launch_bounds__(256, 1)
gemm_hmma_kernel(float* __restrict__ out) {
    extern __shared__ __nv_bfloat16 sh[];
    const uint32_t sbase = smem_u32(sh);

    const int tid  = threadIdx.x;
    const int lane = tid & 31;
    const int wid  = tid >> 5;
    const int mw   = wid >> 1;           // 0..3  (M warp)
    const int nw   = wid & 1;            // 0..1  (N warp)
    const int bm   = blockIdx.y * BM;
    const int bn   = blockIdx.x * BN;

    const int ar0 = tid >> 2,          akb0 = (tid & 3) * 8;
    const int ar1 = (tid + 256) >> 2;
    const int br  = tid >> 2,          bkb  = (tid & 3) * 8;

    const __nv_bfloat16* gAhi0 = d_xhi + (size_t)(bm + ar0) * NIN + akb0;
    const __nv_bfloat16* gAlo0 = d_xlo + (size_t)(bm + ar0) * NIN + akb0;
    const __nv_bfloat16* gAhi1 = d_xhi + (size_t)(bm + ar1) * NIN + akb0;
    const __nv_bfloat16* gAlo1 = d_xlo + (size_t)(bm + ar1) * NIN + akb0;
    const __nv_bfloat16* gBhi  = d_Whi + (size_t)(bn + br) * NIN + bkb;
    const __nv_bfloat16* gBlo  = d_Wlo + (size_t)(bn + br) * NIN + bkb;

    const uint32_t dA0 = (uint32_t)(ar0 * LDH + akb0) * 2;
    const uint32_t dA1 = (uint32_t)(ar1 * LDH + akb0) * 2;
    const uint32_t dB  = (uint32_t)(br  * LDH + bkb)  * 2;

#define ISSUE(kk)                                                              \
    do {                                                                       \
        const uint32_t st_ = sbase + (uint32_t)((kk) & (STAGES - 1)) * (STG_H * 2); \
        const int kg_ = (kk) * BK;                                             \
        cp16(st_ + OFF_AHI * 2 + dA0, gAhi0 + kg_);                            \
        cp16(st_ + OFF_AHI * 2 + dA1, gAhi1 + kg_);                            \
        cp16(st_ + OFF_ALO * 2 + dA0, gAlo0 + kg_);                            \
        cp16(st_ + OFF_ALO * 2 + dA1, gAlo1 + kg_);                            \
        cp16(st_ + OFF_BHI * 2 + dB,  gBhi  + kg_);                            \
        cp16(st_ + OFF_BLO * 2 + dB,  gBlo  + kg_);                            \
        asm volatile("cp.async.commit_group;" ::: "memory");                   \
    } while (0)

    uint32_t aoff[2][2];
#pragma unroll
    for (int f = 0; f < 2; ++f)
#pragma unroll
        for (int s = 0; s < 2; ++s)
            aoff[f][s] = (uint32_t)((mw * 32 + f * 16 + (lane & 15)) * LDH
                                    + s * 16 + (lane >> 4) * 8) * 2;
    uint32_t boff[2][2];
#pragma unroll
    for (int p = 0; p < 2; ++p)
#pragma unroll
        for (int s = 0; s < 2; ++s)
            boff[p][s] = (uint32_t)((nw * 32 + p * 16 + (lane & 7) + ((lane & 16) >> 1)) * LDH
                                    + s * 16 + (((lane >> 3) & 1) * 8)) * 2;

    float acc[2][4][4] = {};

    ISSUE(0); ISSUE(1); ISSUE(2);

    for (int k = 0; k < NKT; ++k) {
        asm volatile("cp.async.wait_group 2;" ::: "memory");
        __syncthreads();

        if (k + 3 < NKT) ISSUE(k + 3);
        else asm volatile("cp.async.commit_group;" ::: "memory");

        const uint32_t st = sbase + (uint32_t)(k & (STAGES - 1)) * (STG_H * 2);
        const uint32_t ahi_b = st + OFF_AHI * 2, alo_b = st + OFF_ALO * 2;
        const uint32_t bhi_b = st + OFF_BHI * 2, blo_b = st + OFF_BLO * 2;

#pragma unroll
        for (int s = 0; s < 2; ++s) {
            uint32_t a_hi[2][4], a_lo[2][4], b_hi[2][4], b_lo[2][4];
            ldsm4(a_hi[0], ahi_b + aoff[0][s]);
            ldsm4(a_hi[1], ahi_b + aoff[1][s]);
            ldsm4(a_lo[0], alo_b + aoff[0][s]);
            ldsm4(a_lo[1], alo_b + aoff[1][s]);
            ldsm4(b_hi[0], bhi_b + boff[0][s]);
            ldsm4(b_hi[1], bhi_b + boff[1][s]);
            ldsm4(b_lo[0], blo_b + boff[0][s]);
            ldsm4(b_lo[1], blo_b + boff[1][s]);
#pragma unroll
            for (int mf = 0; mf < 2; ++mf)
#pragma unroll
                for (int nf = 0; nf < 4; ++nf) {
                    const int p = nf >> 1, q = (nf & 1) * 2;
                    mma_bf16(acc[mf][nf], a_hi[mf], b_hi[p][q], b_hi[p][q + 1]);
                    mma_bf16(acc[mf][nf], a_hi[mf], b_lo[p][q], b_lo[p][q + 1]);
                    mma_bf16(acc[mf][nf], a_lo[mf], b_hi[p][q], b_hi[p][q + 1]);
                }
        }
        __syncthreads();
    }
#undef ISSUE

#pragma unroll
    for (int mf = 0; mf < 2; ++mf) {
        const int row0 = bm + mw * 32 + mf * 16 + (lane >> 2);
#pragma unroll
        for (int nf = 0; nf < 4; ++nf) {
            const int col = bn + nw * 32 + nf * 8 + (lane & 3) * 2;
            *reinterpret_cast<float2*>(&out[(size_t)row0 * NOUT + col]) =
                make_float2(acc[mf][nf][0], acc[mf][nf][1]);
            *reinterpret_cast<float2*>(&out[(size_t)(row0 + 8) * NOUT + col]) =
                make_float2(acc[mf][nf][2], acc[mf][nf][3]);
        }
    }
}

// ---------------------------------------------------------------------------
// Launch: zero -> scatter -> xsplit -> HMMA GEMM (default stream, capturable)
// ---------------------------------------------------------------------------
extern "C" void kernel_launch(void* const* d_in, const int* in_sizes, int n_in,
                              void* d_out, int out_size) {
    const float* x    = (const float*)d_in[0];
    const float* vals = (const float*)d_in[1];
    const int*   idx  = (const int*)d_in[2];
    float*       out  = (float*)d_out;

    // 64MB over 16B stores = 4,194,304 threads = 16384 blocks
    zero_w_kernel<<<16384, 256>>>();
    scatter_kernel<<<NSPARSE / 4 / 256, 256>>>(vals, idx);
    xsplit_kernel<<<(TOKENS * NIN) / 256, 256>>>(x);

    static bool configured = false;
    if (!configured) {
        cudaFuncSetAttribute(gemm_hmma_kernel,
                             cudaFuncAttributeMaxDynamicSharedMemorySize, SMEM_BYTES);
        configured = true;
    }
    dim3 grid(NOUT / BN, TOKENS / BM);   // 64 x 2 = 128 CTAs
    gemm_hmma_kernel<<<grid, 256, SMEM_BYTES>>>(out);
}

// round 5
// speedup vs baseline: 3.0546x; 1.5515x over previous
#include <cuda_runtime.h>
#include <cuda_fp16.h>
#include <cstdint>

#define TOKENS  256
#define NOUT    4096
#define NIN     4096
#define NSPARSE 8388608

// ---------------------------------------------------------------------------
// Scratch (allocation-free rule: __device__ globals)
// ---------------------------------------------------------------------------
__device__ __half d_W[(size_t)NOUT * NIN];    // 32 MB, fp16 weights
__device__ __half d_xhi[TOKENS * NIN];
__device__ __half d_xlo[TOKENS * NIN];

// ---------------------------------------------------------------------------
// Stage 0: zero W (32 MB) with 16B stores. 2,097,152 threads.
// ---------------------------------------------------------------------------
__global__ void zero_w_kernel() {
    const size_t i = (size_t)blockIdx.x * blockDim.x + threadIdx.x;
    reinterpret_cast<uint4*>(d_W)[i] = make_uint4(0u, 0u, 0u, 0u);
}

// ---------------------------------------------------------------------------
// Stage 0b: zero the output (4 MB) for the split-K atomic epilogue.
// ---------------------------------------------------------------------------
__global__ void zero_out_kernel(float* __restrict__ out) {
    const size_t i = (size_t)blockIdx.x * blockDim.x + threadIdx.x;
    reinterpret_cast<uint4*>(out)[i] = make_uint4(0u, 0u, 0u, 0u);
}

// ---------------------------------------------------------------------------
// Stage 1: scatter sparse values as fp16 (gaps already zero).
// 4 elements/thread via vector loads; one 2B store per element.
// ---------------------------------------------------------------------------
__global__ void scatter_kernel(const float* __restrict__ vals,
                               const int*   __restrict__ idx) {
    const int i = blockIdx.x * blockDim.x + threadIdx.x;   // < NSPARSE/4
    const int4   ix = reinterpret_cast<const int4*>(idx)[i];
    const float4 v  = reinterpret_cast<const float4*>(vals)[i];
    d_W[(unsigned)ix.x] = __float2half(v.x);
    d_W[(unsigned)ix.y] = __float2half(v.y);
    d_W[(unsigned)ix.z] = __float2half(v.z);
    d_W[(unsigned)ix.w] = __float2half(v.w);
}

// ---------------------------------------------------------------------------
// Stage 2: split x into fp16 hi/lo (hi+lo carries ~22 mantissa bits).
// ---------------------------------------------------------------------------
__global__ void xsplit_kernel(const float* __restrict__ x) {
    int i = blockIdx.x * blockDim.x + threadIdx.x;
    float v = x[i];
    __half hi = __float2half(v);
    d_xhi[i] = hi;
    d_xlo[i] = __float2half(v - __half2float(hi));
}

// ---------------------------------------------------------------------------
// Stage 3: HMMA fp16 NT GEMM with split-K=2: out += (xhi + xlo) @ W^T.
// CTA 128x64, BK=32, 256 threads (8 warps, 4x2), 4-stage cp.async pipeline,
// 2 products per K-slice (Ahi*B + Alo*B), atomicAdd epilogue (2 commutative
// adds per element -> deterministic).
// ---------------------------------------------------------------------------
constexpr int BM = 128;
constexpr int BN = 64;
constexpr int BK = 32;
constexpr int KSPLIT  = 2;
constexpr int STAGES  = 4;
constexpr int NKT     = NIN / BK / KSPLIT;   // 64 k-tiles per CTA
constexpr int LDH     = BK + 8;              // 40 halves/row -> conflict-free ldmatrix
constexpr int A_H     = BM * LDH;            // per A tile (halves)
constexpr int B_H     = BN * LDH;
constexpr int STG_H   = 2 * A_H + B_H;       // Ahi, Alo, B
constexpr int OFF_AHI = 0;
constexpr int OFF_ALO = A_H;
constexpr int OFF_B   = 2 * A_H;
constexpr int SMEM_BYTES = STAGES * STG_H * 2;   // 4*25600 = 102400

__device__ __forceinline__ uint32_t smem_u32(const void* p) {
    uint32_t a;
    asm("{ .reg .u64 t; cvta.to.shared.u64 t, %1; cvt.u32.u64 %0, t; }" : "=r"(a) : "l"(p));
    return a;
}
__device__ __forceinline__ void cp16(uint32_t dst, const void* src) {
    asm volatile("cp.async.cg.shared.global [%0], [%1], 16;" :: "r"(dst), "l"(src));
}
__device__ __forceinline__ void ldsm4(uint32_t r[4], uint32_t addr) {
    asm volatile("ldmatrix.sync.aligned.m8n8.x4.shared.b16 {%0,%1,%2,%3},[%4];"
                 : "=r"(r[0]), "=r"(r[1]), "=r"(r[2]), "=r"(r[3]) : "r"(addr));
}
__device__ __forceinline__ void mma_f16(float c[4], const uint32_t a[4],
                                        uint32_t b0, uint32_t b1) {
    asm volatile(
        "mma.sync.aligned.m16n8k16.row.col.f32.f16.f16.f32 "
        "{%0,%1,%2,%3},{%4,%5,%6,%7},{%8,%9},{%0,%1,%2,%3};"
        : "+f"(c[0]), "+f"(c[1]), "+f"(c[2]), "+f"(c[3])
        : "r"(a[0]), "r"(a[1]), "r"(a[2]), "r"(a[3]), "r"(b0), "r"(b1));
}

__global__ void __launch_bounds__(256, 2)
gemm_hmma_kernel(float* __restrict__ out) {
    extern __shared__ __half sh[];
    const uint32_t sbase = smem_u32(sh);

    const int tid  = threadIdx.x;
    const int lane = tid & 31;
    const int wid  = tid >> 5;
    const int mw   = wid >> 1;           // 0..3 (M warp)
    const int nw   = wid & 1;            // 0..1 (N warp)
    const int bm   = blockIdx.y * BM;
    const int bn   = blockIdx.x * BN;
    const int kv   = blockIdx.z;         // split-K index
    const int kbase = kv * NKT;          // first k-tile of this CTA

    // A tile: 512 16B-chunks (row=c>>2, kblk=(c&3)*8); thread t owns c=t, t+256.
    // B tile: 256 chunks; thread t owns c=t.
    const int ar0 = tid >> 2,          akb0 = (tid & 3) * 8;
    const int ar1 = (tid + 256) >> 2;
    const int br  = tid >> 2,          bkb  = (tid & 3) * 8;

    const __half* gAhi0 = d_xhi + (size_t)(bm + ar0) * NIN + akb0;
    const __half* gAlo0 = d_xlo + (size_t)(bm + ar0) * NIN + akb0;
    const __half* gAhi1 = d_xhi + (size_t)(bm + ar1) * NIN + akb0;
    const __half* gAlo1 = d_xlo + (size_t)(bm + ar1) * NIN + akb0;
    const __half* gB    = d_W   + (size_t)(bn + br) * NIN + bkb;

    const uint32_t dA0 = (uint32_t)(ar0 * LDH + akb0) * 2;
    const uint32_t dA1 = (uint32_t)(ar1 * LDH + akb0) * 2;
    const uint32_t dB  = (uint32_t)(br  * LDH + bkb)  * 2;

#define ISSUE(kk)                                                              \
    do {                                                                       \
        const uint32_t st_ = sbase + (uint32_t)((kk) & (STAGES - 1)) * (STG_H * 2); \
        const int kg_ = (kbase + (kk)) * BK;                                   \
        cp16(st_ + OFF_AHI * 2 + dA0, gAhi0 + kg_);                            \
        cp16(st_ + OFF_AHI * 2 + dA1, gAhi1 + kg_);                            \
        cp16(st_ + OFF_ALO * 2 + dA0, gAlo0 + kg_);                            \
        cp16(st_ + OFF_ALO * 2 + dA1, gAlo1 + kg_);                            \
        cp16(st_ + OFF_B   * 2 + dB,  gB    + kg_);                            \
        asm volatile("cp.async.commit_group;" ::: "memory");                   \
    } while (0)

    // ldmatrix per-lane byte offsets (within a tile region)
    uint32_t aoff[2][2];
#pragma unroll
    for (int f = 0; f < 2; ++f)
#pragma unroll
        for (int s = 0; s < 2; ++s)
            aoff[f][s] = (uint32_t)((mw * 32 + f * 16 + (lane & 15)) * LDH
                                    + s * 16 + (lane >> 4) * 8) * 2;
    uint32_t boff[2][2];
#pragma unroll
    for (int p = 0; p < 2; ++p)
#pragma unroll
        for (int s = 0; s < 2; ++s)
            boff[p][s] = (uint32_t)((nw * 32 + p * 16 + (lane & 7) + ((lane & 16) >> 1)) * LDH
                                    + s * 16 + (((lane >> 3) & 1) * 8)) * 2;

    float acc[2][4][4] = {};

    ISSUE(0); ISSUE(1); ISSUE(2);

    for (int k = 0; k < NKT; ++k) {
        asm volatile("cp.async.wait_group 2;" ::: "memory");
        __syncthreads();

        if (k + 3 < NKT) ISSUE(k + 3);
        else asm volatile("cp.async.commit_group;" ::: "memory");

        const uint32_t st = sbase + (uint32_t)(k & (STAGES - 1)) * (STG_H * 2);
        const uint32_t ahi_b = st + OFF_AHI * 2, alo_b = st + OFF_ALO * 2;
        const uint32_t b_b   = st + OFF_B * 2;

#pragma unroll
        for (int s = 0; s < 2; ++s) {            // two k16 slices per BK=32
            uint32_t a_hi[2][4], a_lo[2][4], b[2][4];
            ldsm4(a_hi[0], ahi_b + aoff[0][s]);
            ldsm4(a_hi[1], ahi_b + aoff[1][s]);
            ldsm4(a_lo[0], alo_b + aoff[0][s]);
            ldsm4(a_lo[1], alo_b + aoff[1][s]);
            ldsm4(b[0],    b_b   + boff[0][s]);
            ldsm4(b[1],    b_b   + boff[1][s]);
#pragma unroll
            for (int mf = 0; mf < 2; ++mf)
#pragma unroll
                for (int nf = 0; nf < 4; ++nf) {
                    const int p = nf >> 1, q = (nf & 1) * 2;
                    mma_f16(acc[mf][nf], a_hi[mf], b[p][q], b[p][q + 1]);
                    mma_f16(acc[mf][nf], a_lo[mf], b[p][q], b[p][q + 1]);
                }
        }
        __syncthreads();
    }
#undef ISSUE

    // Split-K epilogue: atomic accumulate (exactly 2 adds/element, commutative
    // -> bitwise deterministic; out pre-zeroed by zero_out_kernel).
#pragma unroll
    for (int mf = 0; mf < 2; ++mf) {
        const int row0 = bm + mw * 32 + mf * 16 + (lane >> 2);
#pragma unroll
        for (int nf = 0; nf < 4; ++nf) {
            const int col = bn + nw * 32 + nf * 8 + (lane & 3) * 2;
            float* p0 = &out[(size_t)row0 * NOUT + col];
            float* p1 = &out[(size_t)(row0 + 8) * NOUT + col];
            atomicAdd(p0,     acc[mf][nf][0]);
            atomicAdd(p0 + 1, acc[mf][nf][1]);
            atomicAdd(p1,     acc[mf][nf][2]);
            atomicAdd(p1 + 1, acc[mf][nf][3]);
        }
    }
}

// ---------------------------------------------------------------------------
// Launch: zero W -> scatter -> xsplit -> zero out -> GEMM (capturable)
// ---------------------------------------------------------------------------
extern "C" void kernel_launch(void* const* d_in, const int* in_sizes, int n_in,
                              void* d_out, int out_size) {
    const float* x    = (const float*)d_in[0];
    const float* vals = (const float*)d_in[1];
    const int*   idx  = (const int*)d_in[2];
    float*       out  = (float*)d_out;

    zero_w_kernel<<<8192, 256>>>();                      // 32MB / 16B / 256
    scatter_kernel<<<NSPARSE / 4 / 256, 256>>>(vals, idx);
    xsplit_kernel<<<(TOKENS * NIN) / 256, 256>>>(x);
    zero_out_kernel<<<(TOKENS * NOUT / 4) / 256, 256>>>(out);

    static bool configured = false;
    if (!configured) {
        cudaFuncSetAttribute(gemm_hmma_kernel,
                             cudaFuncAttributeMaxDynamicSharedMemorySize, SMEM_BYTES);
        configured = true;
    }
    dim3 grid(NOUT / BN, TOKENS / BM, KSPLIT);   // 64 x 2 x 2 = 256 CTAs
    gemm_hmma_kernel<<<grid, 256, SMEM_BYTES>>>(out);
}

// round 6
// speedup vs baseline: 4.6662x; 1.5276x over previous
#include <cuda_runtime.h>
#include <cuda_fp16.h>
#include <cstdint>

#define TOKENS  256
#define NOUT    4096
#define NIN     4096
#define NSPARSE 8388608

// ---------------------------------------------------------------------------
// Scratch (allocation-free rule: __device__ globals)
// ---------------------------------------------------------------------------
__device__ __half d_W[(size_t)NOUT * NIN];    // 32 MB fp16 weights
__device__ __half d_x16[TOKENS * NIN];        // 2 MB fp16 activations

// ---------------------------------------------------------------------------
// Stage 0: zero W (32 MB) with 16B stores.
// ---------------------------------------------------------------------------
__global__ void zero_w_kernel() {
    const size_t i = (size_t)blockIdx.x * blockDim.x + threadIdx.x;
    reinterpret_cast<uint4*>(d_W)[i] = make_uint4(0u, 0u, 0u, 0u);
}

// ---------------------------------------------------------------------------
// Stage 0b: zero the output (4 MB) for the split-K atomic epilogue.
// ---------------------------------------------------------------------------
__global__ void zero_out_kernel(float* __restrict__ out) {
    const size_t i = (size_t)blockIdx.x * blockDim.x + threadIdx.x;
    reinterpret_cast<uint4*>(out)[i] = make_uint4(0u, 0u, 0u, 0u);
}

// ---------------------------------------------------------------------------
// Stage 1: scatter sparse values as fp16 (gaps already zero).
// ---------------------------------------------------------------------------
__global__ void scatter_kernel(const float* __restrict__ vals,
                               const int*   __restrict__ idx) {
    const int i = blockIdx.x * blockDim.x + threadIdx.x;   // < NSPARSE/4
    const int4   ix = reinterpret_cast<const int4*>(idx)[i];
    const float4 v  = reinterpret_cast<const float4*>(vals)[i];
    d_W[(unsigned)ix.x] = __float2half(v.x);
    d_W[(unsigned)ix.y] = __float2half(v.y);
    d_W[(unsigned)ix.z] = __float2half(v.z);
    d_W[(unsigned)ix.w] = __float2half(v.w);
}

// ---------------------------------------------------------------------------
// Stage 2: convert x to fp16 (4 elems/thread, vectorized).
// ---------------------------------------------------------------------------
__global__ void xconv_kernel(const float* __restrict__ x) {
    const int i = blockIdx.x * blockDim.x + threadIdx.x;   // < TOKENS*NIN/4
    const float4 v = reinterpret_cast<const float4*>(x)[i];
    __half2* dst = reinterpret_cast<__half2*>(d_x16) + 2 * i;
    dst[0] = __floats2half2_rn(v.x, v.y);
    dst[1] = __floats2half2_rn(v.z, v.w);
}

// ---------------------------------------------------------------------------
// Stage 3: single-product HMMA fp16 NT GEMM, split-K=2.
// CTA 128x64, BK=32, 256 threads (8 warps, 4x2), 6-stage cp.async pipeline,
// atomicAdd epilogue (exactly 2 commutative adds/element -> deterministic).
// ---------------------------------------------------------------------------
constexpr int BM = 128;
constexpr int BN = 64;
constexpr int BK = 32;
constexpr int KSPLIT  = 2;
constexpr int STAGES  = 6;
constexpr int NKT     = NIN / BK / KSPLIT;   // 64 k-tiles per CTA
constexpr int LDH     = BK + 8;              // 40 halves/row -> conflict-free ldmatrix
constexpr int A_H     = BM * LDH;
constexpr int B_H     = BN * LDH;
constexpr int STG_H   = A_H + B_H;           // A, B = 7680 halves / stage
constexpr int OFF_A   = 0;
constexpr int OFF_B   = A_H;
constexpr int SMEM_BYTES = STAGES * STG_H * 2;   // 92160

__device__ __forceinline__ uint32_t smem_u32(const void* p) {
    uint32_t a;
    asm("{ .reg .u64 t; cvta.to.shared.u64 t, %1; cvt.u32.u64 %0, t; }" : "=r"(a) : "l"(p));
    return a;
}
__device__ __forceinline__ void cp16(uint32_t dst, const void* src) {
    asm volatile("cp.async.cg.shared.global [%0], [%1], 16;" :: "r"(dst), "l"(src));
}
__device__ __forceinline__ void ldsm4(uint32_t r[4], uint32_t addr) {
    asm volatile("ldmatrix.sync.aligned.m8n8.x4.shared.b16 {%0,%1,%2,%3},[%4];"
                 : "=r"(r[0]), "=r"(r[1]), "=r"(r[2]), "=r"(r[3]) : "r"(addr));
}
__device__ __forceinline__ void mma_f16(float c[4], const uint32_t a[4],
                                        uint32_t b0, uint32_t b1) {
    asm volatile(
        "mma.sync.aligned.m16n8k16.row.col.f32.f16.f16.f32 "
        "{%0,%1,%2,%3},{%4,%5,%6,%7},{%8,%9},{%0,%1,%2,%3};"
        : "+f"(c[0]), "+f"(c[1]), "+f"(c[2]), "+f"(c[3])
        : "r"(a[0]), "r"(a[1]), "r"(a[2]), "r"(a[3]), "r"(b0), "r"(b1));
}

__global__ void __launch_bounds__(256, 2)
gemm_hmma_kernel(float* __restrict__ out) {
    extern __shared__ __half sh[];
    const uint32_t sbase = smem_u32(sh);

    const int tid  = threadIdx.x;
    const int lane = tid & 31;
    const int wid  = tid >> 5;
    const int mw   = wid >> 1;           // 0..3 (M warp)
    const int nw   = wid & 1;            // 0..1 (N warp)
    const int bm   = blockIdx.y * BM;
    const int bn   = blockIdx.x * BN;
    const int kbase = blockIdx.z * NKT;  // split-K base k-tile

    // A tile: 512 16B-chunks (row=c>>2, kblk=(c&3)*8); thread t owns c=t, t+256.
    // B tile: 256 chunks; thread t owns c=t.
    const int ar0 = tid >> 2,          akb0 = (tid & 3) * 8;
    const int ar1 = (tid + 256) >> 2;
    const int br  = tid >> 2,          bkb  = (tid & 3) * 8;

    const __half* gA0 = d_x16 + (size_t)(bm + ar0) * NIN + akb0;
    const __half* gA1 = d_x16 + (size_t)(bm + ar1) * NIN + akb0;
    const __half* gB  = d_W   + (size_t)(bn + br) * NIN + bkb;

    const uint32_t dA0 = (uint32_t)(ar0 * LDH + akb0) * 2;
    const uint32_t dA1 = (uint32_t)(ar1 * LDH + akb0) * 2;
    const uint32_t dB  = (uint32_t)(br  * LDH + bkb)  * 2;

#define ISSUE(kk)                                                              \
    do {                                                                       \
        const uint32_t st_ = sbase + (uint32_t)((kk) % STAGES) * (STG_H * 2);  \
        const int kg_ = (kbase + (kk)) * BK;                                   \
        cp16(st_ + OFF_A * 2 + dA0, gA0 + kg_);                                \
        cp16(st_ + OFF_A * 2 + dA1, gA1 + kg_);                                \
        cp16(st_ + OFF_B * 2 + dB,  gB  + kg_);                                \
        asm volatile("cp.async.commit_group;" ::: "memory");                   \
    } while (0)

    // ldmatrix per-lane byte offsets (within a tile region)
    uint32_t aoff[2][2];
#pragma unroll
    for (int f = 0; f < 2; ++f)
#pragma unroll
        for (int s = 0; s < 2; ++s)
            aoff[f][s] = (uint32_t)((mw * 32 + f * 16 + (lane & 15)) * LDH
                                    + s * 16 + (lane >> 4) * 8) * 2;
    uint32_t boff[2][2];
#pragma unroll
    for (int p = 0; p < 2; ++p)
#pragma unroll
        for (int s = 0; s < 2; ++s)
            boff[p][s] = (uint32_t)((nw * 32 + p * 16 + (lane & 7) + ((lane & 16) >> 1)) * LDH
                                    + s * 16 + (((lane >> 3) & 1) * 8)) * 2;

    float acc[2][4][4] = {};

    ISSUE(0); ISSUE(1); ISSUE(2); ISSUE(3); ISSUE(4);

    for (int k = 0; k < NKT; ++k) {
        asm volatile("cp.async.wait_group 4;" ::: "memory");
        __syncthreads();

        if (k + 5 < NKT) ISSUE(k + 5);
        else asm volatile("cp.async.commit_group;" ::: "memory");

        const uint32_t st = sbase + (uint32_t)(k % STAGES) * (STG_H * 2);
        const uint32_t a_b = st + OFF_A * 2;
        const uint32_t b_b = st + OFF_B * 2;

#pragma unroll
        for (int s = 0; s < 2; ++s) {            // two k16 slices per BK=32
            uint32_t a[2][4], b[2][4];
            ldsm4(a[0], a_b + aoff[0][s]);
            ldsm4(a[1], a_b + aoff[1][s]);
            ldsm4(b[0], b_b + boff[0][s]);
            ldsm4(b[1], b_b + boff[1][s]);
#pragma unroll
            for (int mf = 0; mf < 2; ++mf)
#pragma unroll
                for (int nf = 0; nf < 4; ++nf) {
                    const int p = nf >> 1, q = (nf & 1) * 2;
                    mma_f16(acc[mf][nf], a[mf], b[p][q], b[p][q + 1]);
                }
        }
        __syncthreads();
    }
#undef ISSUE

    // Split-K epilogue: atomic accumulate (2 adds/element, deterministic).
#pragma unroll
    for (int mf = 0; mf < 2; ++mf) {
        const int row0 = bm + mw * 32 + mf * 16 + (lane >> 2);
#pragma unroll
        for (int nf = 0; nf < 4; ++nf) {
            const int col = bn + nw * 32 + nf * 8 + (lane & 3) * 2;
            float* p0 = &out[(size_t)row0 * NOUT + col];
            float* p1 = &out[(size_t)(row0 + 8) * NOUT + col];
            atomicAdd(p0,     acc[mf][nf][0]);
            atomicAdd(p0 + 1, acc[mf][nf][1]);
            atomicAdd(p1,     acc[mf][nf][2]);
            atomicAdd(p1 + 1, acc[mf][nf][3]);
        }
    }
}

// ---------------------------------------------------------------------------
// Launch: zero W -> scatter -> xconv -> zero out -> GEMM (capturable)
// ---------------------------------------------------------------------------
extern "C" void kernel_launch(void* const* d_in, const int* in_sizes, int n_in,
                              void* d_out, int out_size) {
    const float* x    = (const float*)d_in[0];
    const float* vals = (const float*)d_in[1];
    const int*   idx  = (const int*)d_in[2];
    float*       out  = (float*)d_out;

    zero_w_kernel<<<8192, 256>>>();                       // 32MB / 16B / 256
    scatter_kernel<<<NSPARSE / 4 / 256, 256>>>(vals, idx);
    xconv_kernel<<<(TOKENS * NIN / 4) / 256, 256>>>(x);
    zero_out_kernel<<<(TOKENS * NOUT / 4) / 256, 256>>>(out);

    static bool configured = false;
    if (!configured) {
        cudaFuncSetAttribute(gemm_hmma_kernel,
                             cudaFuncAttributeMaxDynamicSharedMemorySize, SMEM_BYTES);
        configured = true;
    }
    dim3 grid(NOUT / BN, TOKENS / BM, KSPLIT);   // 64 x 2 x 2 = 256 CTAs
    gemm_hmma_kernel<<<grid, 256, SMEM_BYTES>>>(out);
}

// round 8
// speedup vs baseline: 4.8617x; 1.0419x over previous
#include <cuda_runtime.h>
#include <cuda_fp16.h>
#include <cstdint>

#define TOKENS  256
#define NOUT    4096
#define NIN     4096
#define NSPARSE 8388608

// ---------------------------------------------------------------------------
// Scratch (allocation-free rule: __device__ globals)
// ---------------------------------------------------------------------------
__device__ __half d_W[(size_t)NOUT * NIN];    // 32 MB fp16 weights
__device__ __half d_x16[TOKENS * NIN];        // 2 MB fp16 activations

// ---------------------------------------------------------------------------
// Stage 0: zero W (32 MB) with 16B stores.
// ---------------------------------------------------------------------------
__global__ void zero_w_kernel() {
    const size_t i = (size_t)blockIdx.x * blockDim.x + threadIdx.x;
    reinterpret_cast<uint4*>(d_W)[i] = make_uint4(0u, 0u, 0u, 0u);
}

// ---------------------------------------------------------------------------
// Stage 1: scatter sparse values as fp16 (gaps already zero).
// ---------------------------------------------------------------------------
__global__ void scatter_kernel(const float* __restrict__ vals,
                               const int*   __restrict__ idx) {
    const int i = blockIdx.x * blockDim.x + threadIdx.x;   // < NSPARSE/4
    const int4   ix = reinterpret_cast<const int4*>(idx)[i];
    const float4 v  = reinterpret_cast<const float4*>(vals)[i];
    d_W[(unsigned)ix.x] = __float2half(v.x);
    d_W[(unsigned)ix.y] = __float2half(v.y);
    d_W[(unsigned)ix.z] = __float2half(v.z);
    d_W[(unsigned)ix.w] = __float2half(v.w);
}

// ---------------------------------------------------------------------------
// Stage 2 (fused): blocks [0, 1024): convert x to fp16 (4 f32/thread,
//   1024*256*4 = 1,048,576 = TOKENS*NIN exactly);
// blocks [1024, 2048): zero out (1024*256*16B = 4MB = TOKENS*NOUT*4B exactly).
// ---------------------------------------------------------------------------
__global__ void prep_kernel(const float* __restrict__ x, float* __restrict__ out) {
    const int b = blockIdx.x;
    if (b < 1024) {
        const int i = b * blockDim.x + threadIdx.x;        // < TOKENS*NIN/4
        const float4 v = reinterpret_cast<const float4*>(x)[i];
        __half2* dst = reinterpret_cast<__half2*>(d_x16) + 2 * i;
        dst[0] = __floats2half2_rn(v.x, v.y);
        dst[1] = __floats2half2_rn(v.z, v.w);
    } else {
        const int i = (b - 1024) * blockDim.x + threadIdx.x;  // < TOKENS*NOUT/4
        reinterpret_cast<uint4*>(out)[i] = make_uint4(0u, 0u, 0u, 0u);
    }
}

// ---------------------------------------------------------------------------
// Stage 3: single-product HMMA fp16 NT GEMM, split-K=2.
// CTA 128x64, BK=32, 256 threads (8 warps, 4x2), 6-stage cp.async pipeline,
// single barrier per k-tile, all-LDSM-then-all-MMA scheduling.
// ---------------------------------------------------------------------------
constexpr int BM = 128;
constexpr int BN = 64;
constexpr int BK = 32;
constexpr int KSPLIT  = 2;
constexpr int STAGES  = 6;
constexpr int NKT     = NIN / BK / KSPLIT;   // 64 k-tiles per CTA
constexpr int LDH     = BK + 8;              // 40 halves/row -> conflict-free ldmatrix
constexpr int A_H     = BM * LDH;
constexpr int B_H     = BN * LDH;
constexpr int STG_H   = A_H + B_H;           // 7680 halves / stage
constexpr int OFF_A   = 0;
constexpr int OFF_B   = A_H;
constexpr int SMEM_BYTES = STAGES * STG_H * 2;   // 92160

__device__ __forceinline__ uint32_t smem_u32(const void* p) {
    uint32_t a;
    asm("{ .reg .u64 t; cvta.to.shared.u64 t, %1; cvt.u32.u64 %0, t; }" : "=r"(a) : "l"(p));
    return a;
}
__device__ __forceinline__ void cp16(uint32_t dst, const void* src) {
    asm volatile("cp.async.cg.shared.global [%0], [%1], 16;" :: "r"(dst), "l"(src));
}
__device__ __forceinline__ void ldsm4(uint32_t r[4], uint32_t addr) {
    asm volatile("ldmatrix.sync.aligned.m8n8.x4.shared.b16 {%0,%1,%2,%3},[%4];"
                 : "=r"(r[0]), "=r"(r[1]), "=r"(r[2]), "=r"(r[3]) : "r"(addr));
}
__device__ __forceinline__ void mma_f16(float c[4], const uint32_t a[4],
                                        uint32_t b0, uint32_t b1) {
    asm volatile(
        "mma.sync.aligned.m16n8k16.row.col.f32.f16.f16.f32 "
        "{%0,%1,%2,%3},{%4,%5,%6,%7},{%8,%9},{%0,%1,%2,%3};"
        : "+f"(c[0]), "+f"(c[1]), "+f"(c[2]), "+f"(c[3])
        : "r"(a[0]), "r"(a[1]), "r"(a[2]), "r"(a[3]), "r"(b0), "r"(b1));
}

__global__ void __launch_bounds__(256, 2)
gemm_hmma_kernel(float* __restrict__ out) {
    extern __shared__ __half sh[];
    const uint32_t sbase = smem_u32(sh);

    const int tid  = threadIdx.x;
    const int lane = tid & 31;
    const int wid  = tid >> 5;
    const int mw   = wid >> 1;           // 0..3 (M warp)
    const int nw   = wid & 1;            // 0..1 (N warp)
    const int bm   = blockIdx.y * BM;
    const int bn   = blockIdx.x * BN;
    const int kbase = blockIdx.z * NKT;  // split-K base k-tile

    const int ar0 = tid >> 2,          akb0 = (tid & 3) * 8;
    const int ar1 = (tid + 256) >> 2;
    const int br  = tid >> 2,          bkb  = (tid & 3) * 8;

    const __half* gA0 = d_x16 + (size_t)(bm + ar0) * NIN + akb0;
    const __half* gA1 = d_x16 + (size_t)(bm + ar1) * NIN + akb0;
    const __half* gB  = d_W   + (size_t)(bn + br) * NIN + bkb;

    const uint32_t dA0 = (uint32_t)(ar0 * LDH + akb0) * 2;
    const uint32_t dA1 = (uint32_t)(ar1 * LDH + akb0) * 2;
    const uint32_t dB  = (uint32_t)(br  * LDH + bkb)  * 2;

#define ISSUE(kk)                                                              \
    do {                                                                       \
        const uint32_t st_ = sbase + (uint32_t)((kk) % STAGES) * (STG_H * 2);  \
        const int kg_ = (kbase + (kk)) * BK;                                   \
        cp16(st_ + OFF_A * 2 + dA0, gA0 + kg_);                                \
        cp16(st_ + OFF_A * 2 + dA1, gA1 + kg_);                                \
        cp16(st_ + OFF_B * 2 + dB,  gB  + kg_);                                \
        asm volatile("cp.async.commit_group;" ::: "memory");                   \
    } while (0)

    uint32_t aoff[2][2];
#pragma unroll
    for (int f = 0; f < 2; ++f)
#pragma unroll
        for (int s = 0; s < 2; ++s)
            aoff[f][s] = (uint32_t)((mw * 32 + f * 16 + (lane & 15)) * LDH
                                    + s * 16 + (lane >> 4) * 8) * 2;
    uint32_t boff[2][2];
#pragma unroll
    for (int p = 0; p < 2; ++p)
#pragma unroll
        for (int s = 0; s < 2; ++s)
            boff[p][s] = (uint32_t)((nw * 32 + p * 16 + (lane & 7) + ((lane & 16) >> 1)) * LDH
                                    + s * 16 + (((lane >> 3) & 1) * 8)) * 2;

    float acc[2][4][4] = {};

    ISSUE(0); ISSUE(1); ISSUE(2); ISSUE(3); ISSUE(4);

    for (int k = 0; k < NKT; ++k) {
        asm volatile("cp.async.wait_group 4;" ::: "memory");
        // Single barrier per k-tile. It both (a) publishes stage k's cp.async
        // data to all warps, and (b) guarantees every warp finished reading
        // stage (k-1)%6 (compute(k-1) precedes this barrier in program order)
        // before ISSUE(k+5) overwrites it below.
        __syncthreads();

        if (k + 5 < NKT) ISSUE(k + 5);
        else asm volatile("cp.async.commit_group;" ::: "memory");

        const uint32_t st = sbase + (uint32_t)(k % STAGES) * (STG_H * 2);
        const uint32_t a_b = st + OFF_A * 2;
        const uint32_t b_b = st + OFF_B * 2;

        // All 8 LDSM up front (both k16 slices), then 16 dependency-free MMAs.
        uint32_t a[2][2][4], b[2][2][4];
#pragma unroll
        for (int s = 0; s < 2; ++s) {
            ldsm4(a[s][0], a_b + aoff[0][s]);
            ldsm4(a[s][1], a_b + aoff[1][s]);
            ldsm4(b[s][0], b_b + boff[0][s]);
            ldsm4(b[s][1], b_b + boff[1][s]);
        }
#pragma unroll
        for (int s = 0; s < 2; ++s)
#pragma unroll
            for (int mf = 0; mf < 2; ++mf)
#pragma unroll
                for (int nf = 0; nf < 4; ++nf) {
                    const int p = nf >> 1, q = (nf & 1) * 2;
                    mma_f16(acc[mf][nf], a[s][mf], b[s][p][q], b[s][p][q + 1]);
                }
    }
#undef ISSUE

    // Split-K epilogue: atomic accumulate (2 adds/element, commutative ->
    // deterministic; out pre-zeroed by prep_kernel).
#pragma unroll
    for (int mf = 0; mf < 2; ++mf) {
        const int row0 = bm + mw * 32 + mf * 16 + (lane >> 2);
#pragma unroll
        for (int nf = 0; nf < 4; ++nf) {
            const int col = bn + nw * 32 + nf * 8 + (lane & 3) * 2;
            float* p0 = &out[(size_t)row0 * NOUT + col];
            float* p1 = &out[(size_t)(row0 + 8) * NOUT + col];
            atomicAdd(p0,     acc[mf][nf][0]);
            atomicAdd(p0 + 1, acc[mf][nf][1]);
            atomicAdd(p1,     acc[mf][nf][2]);
            atomicAdd(p1 + 1, acc[mf][nf][3]);
        }
    }
}

// ---------------------------------------------------------------------------
// Launch: zero W -> scatter -> prep (xconv + zero out) -> GEMM (capturable)
// ---------------------------------------------------------------------------
extern "C" void kernel_launch(void* const* d_in, const int* in_sizes, int n_in,
                              void* d_out, int out_size) {
    const float* x    = (const float*)d_in[0];
    const float* vals = (const float*)d_in[1];
    const int*   idx  = (const int*)d_in[2];
    float*       out  = (float*)d_out;

    zero_w_kernel<<<8192, 256>>>();                       // 32MB / 16B / 256
    scatter_kernel<<<NSPARSE / 4 / 256, 256>>>(vals, idx);
    prep_kernel<<<2048, 256>>>(x, out);                   // xconv [0,1024) + zero out [1024,2048)

    static bool configured = false;
    if (!configured) {
        cudaFuncSetAttribute(gemm_hmma_kernel,
                             cudaFuncAttributeMaxDynamicSharedMemorySize, SMEM_BYTES);
        configured = true;
    }
    dim3 grid(NOUT / BN, TOKENS / BM, KSPLIT);   // 64 x 2 x 2 = 256 CTAs
    gemm_hmma_kernel<<<grid, 256, SMEM_BYTES>>>(out);
}